// round 13
// baseline (speedup 1.0000x reference)
#include <cuda_runtime.h>
#include <cuda_fp16.h>
#include <cstdint>
#include <math.h>

#define BATCH 1024
#define HID   1024
#define NGATE 3072
#define INSZ  55
#define KPAD  64
#define SRC_STEPS 49
#define TGT_STEPS 25
#define TOT_STEPS 74
#define OUT_STRIDE (TGT_STEPS * INSZ)   // 1375
#define NCTA 128
#define NTHR 384

// ---------------- device scratch (no allocs allowed) ----------------
__device__ __align__(16) float g_h0[BATCH * HID];
__device__ __align__(16) float g_h1[BATCH * HID];
__device__ __align__(16) __half g_h0h[BATCH * HID];
__device__ __align__(16) __half g_h1h[BATCH * HID];
__device__ __align__(16) __half g_whh_h[NGATE * HID];   // fp16 Whh
__device__ __align__(16) __half g_wih_h[NGATE * KPAD];  // fp16 Wih (padded K)
__device__ __align__(16) __half g_encx_h[SRC_STEPS * BATCH * KPAD];
__device__ __align__(16) __half g_decx_h[TGT_STEPS * BATCH * KPAD];
__device__ int g_bar_ctr;               // FULL-GRID barrier (lockstep = L2 reuse)
__device__ int g_fc_ctr[16 * 32];       // group-local FC completion counters

// ---------------- PTX helpers (sm_80-class; valid on base sm_103) ----------
__device__ __forceinline__ uint32_t smem_u32(const void* p) {
    uint32_t a;
    asm("{ .reg .u64 t; cvta.to.shared.u64 t, %1; cvt.u32.u64 %0, t; }" : "=r"(a) : "l"(p));
    return a;
}
__device__ __forceinline__ void cp16(uint32_t dst, const void* src) {
    asm volatile("cp.async.cg.shared.global [%0], [%1], 16;"
                 :: "r"(dst), "l"(__cvta_generic_to_global(src)) : "memory");
}
#define CP_COMMIT() asm volatile("cp.async.commit_group;" ::: "memory")
#define CP_WAIT(n)  asm volatile("cp.async.wait_group %0;" :: "n"(n) : "memory")

__device__ __forceinline__ void ldsm4(uint32_t* r, uint32_t addr) {
    asm volatile("ldmatrix.sync.aligned.m8n8.x4.shared.b16 {%0,%1,%2,%3}, [%4];"
        : "=r"(r[0]), "=r"(r[1]), "=r"(r[2]), "=r"(r[3]) : "r"(addr));
}
__device__ __forceinline__ void mma16816(float* c, const uint32_t* a, uint32_t b0, uint32_t b1) {
    asm volatile("mma.sync.aligned.m16n8k16.row.col.f32.f16.f16.f32 "
        "{%0,%1,%2,%3}, {%4,%5,%6,%7}, {%8,%9}, {%0,%1,%2,%3};"
        : "+f"(c[0]), "+f"(c[1]), "+f"(c[2]), "+f"(c[3])
        : "r"(a[0]), "r"(a[1]), "r"(a[2]), "r"(a[3]), "r"(b0), "r"(b1));
}

__device__ __forceinline__ float fsig(float x) {
    return __fdividef(1.f, 1.f + __expf(-x));
}
__device__ __forceinline__ float ftanh(float x) {
    return 1.f - __fdividef(2.f, __expf(2.f * x) + 1.f);
}

// ---------------- geometry ----------------
// CTA: 128 batch rows x 64 hidden cols (= 192 gate-cols). 384 thr, 12 warps.
// warpM = wid&3 (32 rows), warpN = wid>>2 (64 gate-cols).
// Stages 0..7: Whh K=128 each; stage 8: Wih K=64 (x). Buffer = it&1.
#define ROWB 272
#define OFF_B 34816
#define STAGE 87040
#define EPW 200                 // epilogue fp32 tile, ALIASED onto stage bufs
#define GIN_OFF (2 * STAGE)     // 174080: smem h_n stash 128 x GINW fp32
#define GINW 66
#define BIAS_OFF (GIN_OFF + 128 * GINW * 4)     // 207872
#define SMEM_BYTES (BIAS_OFF + 4 * 64 * 4)      // 208896

// ---------------------------------------------------------------------------
// Persistent kernel: all 74 GRU steps + 25 decoder FC steps, one launch.
// ---------------------------------------------------------------------------
__global__ __launch_bounds__(NTHR, 1)
void seq2seq_persistent(const float* __restrict__ dec,
                        const float* __restrict__ bih, const float* __restrict__ bhh,
                        const float* __restrict__ fcw, const float* __restrict__ fcb,
                        float* __restrict__ out)
{
    extern __shared__ char smem[];
    const uint32_t sb = smem_u32(smem);
    const int tid = threadIdx.x;
    const int lane = tid & 31, wid = tid >> 5;
    const int warpM = wid & 3, warpN = wid >> 2;   // warpN 0..2
    const int nT = blockIdx.x & 15, mT = blockIdx.x >> 4;
    const int mBase = mT * 128, nBase = nT * 64;
    volatile int* fcp = &g_fc_ctr[mT * 32];

    float* hf[2] = {g_h0, g_h1};
    __half* hsh[2] = {g_h0h, g_h1h};
    float* sgin = (float*)(smem + GIN_OFF);
    float* sbias = (float*)(smem + BIAS_OFF);   // [4][64]: r, z, n_hh, n_ih

    if (tid < 64) {
        int n = nBase + tid;
        sbias[tid]       = bih[n] + bhh[n];
        sbias[64 + tid]  = bih[HID + n] + bhh[HID + n];
        sbias[128 + tid] = bhh[2 * HID + n];
        sbias[192 + tid] = bih[2 * HID + n];
    }
    __syncthreads();

    // ldsm lane addressing (within stage buffer)
    const int arow = warpM * 32 + (lane & 15);
    const int acolh = (lane >> 4) << 3;
    const int bn = (lane & 7) + ((lane >> 4) << 3);
    const int bkh = ((lane >> 3) & 1) << 3;
    const uint32_t a_lofs = arow * ROWB + acolh * 2;
    const uint32_t b_lofs = (warpN * 64 + bn) * ROWB + bkh * 2;

    // ---- stage loaders ----
    auto load_whh = [&](const __half* hp, int it) {
        const uint32_t st = sb + (uint32_t)(it & 1) * STAGE;
        const int k0 = it * 128;
        for (int i = tid; i < 2048; i += NTHR) {         // A: 128r x 16c
            int row = i >> 4, c = i & 15;
            cp16(st + row * ROWB + c * 16,
                 hp + (long)(mBase + row) * HID + k0 + c * 8);
        }
        for (int i = tid; i < 3072; i += NTHR) {         // B: 192r x 16c
            int grow = i >> 4, c = i & 15;
            long wrow = (long)((grow >> 6) * HID + nBase + (grow & 63));
            cp16(st + OFF_B + grow * ROWB + c * 16,
                 g_whh_h + wrow * HID + k0 + c * 8);
        }
        CP_COMMIT();
    };
    auto load_wih = [&](const __half* xp) {
        const uint32_t st = sb;     // stage 8 -> buf 0
        for (int i = tid; i < 1024; i += NTHR) {         // A: 128r x 8c
            int row = i >> 3, c = i & 7;
            cp16(st + row * ROWB + c * 16,
                 xp + (long)(mBase + row) * KPAD + c * 8);
        }
        for (int i = tid; i < 1536; i += NTHR) {         // B: 192r x 8c
            int grow = i >> 3, c = i & 7;
            long wrow = (long)((grow >> 6) * HID + nBase + (grow & 63));
            cp16(st + OFF_B + grow * ROWB + c * 16,
                 g_wih_h + wrow * KPAD + c * 8);
        }
        CP_COMMIT();
    };

    int cur = 0, nbar = 0;
    bool pre0 = false;

    for (int t = 0; t < TOT_STEPS; t++) {
        const __half* ah = hsh[cur];
        const __half* xh = (t < SRC_STEPS)
            ? g_encx_h + (long)t * BATCH * KPAD
            : g_decx_h + (long)(t - SRC_STEPS) * BATCH * KPAD;

        float acc[2][8][4];
#pragma unroll
        for (int a0 = 0; a0 < 2; a0++)
#pragma unroll
            for (int i = 0; i < 8; i++)
#pragma unroll
                for (int j = 0; j < 4; j++) acc[a0][i][j] = 0.f;

        if (!pre0) load_whh(ah, 0);
        pre0 = false;

        // compile-time-unrollable compute bodies
        auto compute = [&](uint32_t st, int kb) {
            uint32_t Af[2][4], Bf[4][4];
            ldsm4(Af[0], st + a_lofs + kb * 32);
            ldsm4(Af[1], st + a_lofs + 16 * ROWB + kb * 32);
            const uint32_t bo = st + OFF_B + b_lofs + kb * 32;
#pragma unroll
            for (int g = 0; g < 4; g++) ldsm4(Bf[g], bo + g * (16 * ROWB));
#pragma unroll
            for (int mf = 0; mf < 2; mf++)
#pragma unroll
                for (int g = 0; g < 4; g++) {
                    mma16816(acc[mf][g * 2],     Af[mf], Bf[g][0], Bf[g][1]);
                    mma16816(acc[mf][g * 2 + 1], Af[mf], Bf[g][2], Bf[g][3]);
                }
        };

        for (int it = 0; it <= 8; it++) {
            if (it < 8) {
                if (it == 7) {
                    // Wih stage prefetch; decoder x needs prior step's FC (group)
                    if (t > SRC_STEPS) {
                        if (tid == 0) {
                            const int tgt = (t - SRC_STEPS) * 16;
                            while (*fcp < tgt) __nanosleep(32);
                            __threadfence();
                        }
                        __syncthreads();
                    }
                    load_wih(xh);
                } else {
                    load_whh(ah, it + 1);
                }
                CP_WAIT(1);
            } else {
                CP_WAIT(0);
            }
            __syncthreads();

            {
                const uint32_t st = sb + (uint32_t)(it & 1) * STAGE;
                if (it < 8) {
#pragma unroll
                    for (int kb = 0; kb < 8; kb++) compute(st, kb);
                } else {
#pragma unroll
                    for (int kb = 0; kb < 4; kb++) compute(st, kb);
                }
            }

            // after last Whh stage: stash h_n (gate-cols 128..191), zero accs;
            // stage 8 (Wih) then deposits i_n into the zeroed slots.
            if (it == 7 && warpN == 2) {
                const int r0 = warpM * 32 + (lane >> 2);
#pragma unroll
                for (int mf = 0; mf < 2; mf++)
#pragma unroll
                    for (int j = 0; j < 8; j++) {
                        int jl = j * 8 + (lane & 3) * 2;
                        int rr = r0 + mf * 16;
                        *(float2*)&sgin[rr * GINW + jl] =
                            make_float2(acc[mf][j][0], acc[mf][j][1]);
                        *(float2*)&sgin[(rr + 8) * GINW + jl] =
                            make_float2(acc[mf][j][2], acc[mf][j][3]);
                        acc[mf][j][0] = acc[mf][j][1] = 0.f;
                        acc[mf][j][2] = acc[mf][j][3] = 0.f;
                    }
            }
            __syncthreads();
        }

        // ---- epilogue: frags -> ep smem (aliases stage bufs), gates, h ----
        float* ep = (float*)smem;
        {
            const int r0 = warpM * 32 + (lane >> 2);
#pragma unroll
            for (int mf = 0; mf < 2; mf++)
#pragma unroll
                for (int j = 0; j < 8; j++) {
                    int c = warpN * 64 + j * 8 + (lane & 3) * 2;
                    int rr = r0 + mf * 16;
                    *(float2*)&ep[rr * EPW + c] =
                        make_float2(acc[mf][j][0], acc[mf][j][1]);
                    *(float2*)&ep[(rr + 8) * EPW + c] =
                        make_float2(acc[mf][j][2], acc[mf][j][3]);
                }
        }
        __syncthreads();

        {
            const float* h_in = hf[cur];
            float* h_out = hf[cur ^ 1];
            __half* hoh = hsh[cur ^ 1];
            for (int i = tid; i < 4096; i += NTHR) {    // pairs
                int m = i >> 5, jp = (i & 31) * 2;
                long gi = (long)(mBase + m) * HID + nBase + jp;
                float2 rr = *(float2*)&ep[m * EPW + jp];
                float2 zz = *(float2*)&ep[m * EPW + 64 + jp];
                float2 ii = *(float2*)&ep[m * EPW + 128 + jp];
                float2 hh = *(float2*)&sgin[m * GINW + jp];
                float2 br = *(float2*)&sbias[jp];
                float2 bz = *(float2*)&sbias[64 + jp];
                float2 bh = *(float2*)&sbias[128 + jp];
                float2 bi = *(float2*)&sbias[192 + jp];
                float2 hp = *(float2*)&h_in[gi];
                float r0 = fsig(rr.x + br.x), r1 = fsig(rr.y + br.y);
                float z0 = fsig(zz.x + bz.x), z1 = fsig(zz.y + bz.y);
                float n0 = ftanh(ii.x + bi.x + r0 * (hh.x + bh.x));
                float n1 = ftanh(ii.y + bi.y + r1 * (hh.y + bh.y));
                float o0 = (1.f - z0) * n0 + z0 * hp.x;
                float o1 = (1.f - z1) * n1 + z1 * hp.y;
                *(float2*)&h_out[gi] = make_float2(o0, o1);
                *(__half2*)&hoh[gi] = __floats2half2_rn(o0, o1);
            }
        }
        cur ^= 1;

        // ---- FULL-GRID barrier (lockstep -> Whh L2 reuse across groups) ----
        nbar++;
        __syncthreads();
        if (tid == 0) {
            __threadfence();
            atomicAdd(&g_bar_ctr, 1);
            while (*(volatile int*)&g_bar_ctr < nbar * NCTA) __nanosleep(32);
            __threadfence();
        }
        __syncthreads();

        // ---- pre-issue next step's stage-0 load (hides fill under FC) ----
        if (t + 1 < TOT_STEPS) {
            load_whh(hsh[cur], 0);
            pre0 = true;
        }

        // ---- decoder FC (overlapped: consumers wait via fc_ctr at stage 7) --
        if (t >= SRC_STEPS) {
            const int td = t - SRC_STEPS;
            const float* hcur = hf[cur];
            if (wid < 8) {
                const int b = blockIdx.x * 8 + wid;
                float hreg[32];
#pragma unroll
                for (int i = 0; i < 32; i++)
                    hreg[i] = __ldcg(&hcur[(long)b * HID + lane + 32 * i]);
                for (int o = 0; o < INSZ; o++) {
                    float s = 0.f;
#pragma unroll
                    for (int i = 0; i < 32; i++)
                        s += hreg[i] * fcw[(long)o * HID + lane + 32 * i];
#pragma unroll
                    for (int off = 16; off; off >>= 1)
                        s += __shfl_xor_sync(0xffffffffu, s, off);
                    if (lane == 0) {
                        float inp = (td == 0) ? dec[(long)b * OUT_STRIDE + o]
                                              : out[(long)b * OUT_STRIDE + (td - 1) * INSZ + o];
                        float v = inp + s + fcb[o];
                        out[(long)b * OUT_STRIDE + td * INSZ + o] = v;
                        if (td < TGT_STEPS - 1) {
                            long x = (long)(td + 1) * BATCH * KPAD + (long)b * KPAD + o;
                            g_decx_h[x] = __float2half_rn(v);
                        }
                    }
                }
                if (td < TGT_STEPS - 1 && lane < KPAD - INSZ) {
                    long x = (long)(td + 1) * BATCH * KPAD + (long)b * KPAD + INSZ + lane;
                    g_decx_h[x] = __float2half_rn(0.f);
                }
            }
            __syncthreads();
            if (tid == 0) {
                __threadfence();
                atomicAdd(&g_fc_ctr[mT * 32], 1);
            }
        }
    }
}

// ---------------- merged prep kernel ----------------
#define P_WHH  ((long)NGATE * HID)
#define P_WIH  ((long)NGATE * KPAD)
#define P_ENC  ((long)SRC_STEPS * BATCH * KPAD)
#define P_DEC  ((long)BATCH * KPAD)
#define P_ST   ((long)BATCH * HID)
#define P_TOT  (P_WHH + P_WIH + P_ENC + P_DEC + P_ST)

__global__ void prep_kernel(const float* __restrict__ Whh, const float* __restrict__ Wih,
                            const float* __restrict__ enc, const float* __restrict__ dec)
{
    long i = (long)blockIdx.x * 256 + threadIdx.x;
    if (blockIdx.x == 0) {
        if (threadIdx.x == 0) g_bar_ctr = 0;
        if (threadIdx.x < 16 * 32) g_fc_ctr[threadIdx.x] = 0;
    }
    if (i < P_WHH) { g_whh_h[i] = __float2half_rn(Whh[i]); return; }
    i -= P_WHH;
    if (i < P_WIH) {
        int row = (int)(i >> 6), k = (int)(i & 63);
        float v = (k < INSZ) ? Wih[(long)row * INSZ + k] : 0.f;
        g_wih_h[i] = __float2half_rn(v);
        return;
    }
    i -= P_WIH;
    if (i < P_ENC) {
        int t = (int)(i / (BATCH * KPAD));
        int r = (int)(i % (BATCH * KPAD));
        int b = r >> 6, k = r & 63;
        float v = (k < INSZ) ? enc[((long)b * 50 + t) * INSZ + k] : 0.f;
        g_encx_h[i] = __float2half_rn(v);
        return;
    }
    i -= P_ENC;
    if (i < P_DEC) {
        int b = (int)(i >> 6), k = (int)(i & 63);
        float v = (k < INSZ) ? dec[(long)b * OUT_STRIDE + k] : 0.f;
        g_decx_h[i] = __float2half_rn(v);
        return;
    }
    i -= P_DEC;
    if (i < P_ST) {
        g_h0[i] = 0.f;
        g_h0h[i] = __float2half_rn(0.f);
    }
}

extern "C" void kernel_launch(void* const* d_in, const int* in_sizes, int n_in,
                              void* d_out, int out_size)
{
    const float* enc = (const float*)d_in[0];
    const float* dec = (const float*)d_in[1];
    const float* Wih = (const float*)d_in[2];
    const float* Whh = (const float*)d_in[3];
    const float* bih = (const float*)d_in[4];
    const float* bhh = (const float*)d_in[5];
    const float* fcw = (const float*)d_in[6];
    const float* fcb = (const float*)d_in[7];
    float* out = (float*)d_out;

    cudaFuncSetAttribute(seq2seq_persistent,
                         cudaFuncAttributeMaxDynamicSharedMemorySize, SMEM_BYTES);

    prep_kernel<<<(int)((P_TOT + 255) / 256), 256>>>(Whh, Wih, enc, dec);
    seq2seq_persistent<<<NCTA, NTHR, SMEM_BYTES>>>(dec, bih, bhh, fcw, fcb, out);
}

// round 14
// speedup vs baseline: 1.1327x; 1.1327x over previous
#include <cuda_runtime.h>
#include <cuda_fp16.h>
#include <cstdint>
#include <math.h>

#define BATCH 1024
#define HID   1024
#define NGATE 3072
#define INSZ  55
#define KPAD  64
#define SRC_STEPS 49
#define TGT_STEPS 25
#define TOT_STEPS 74
#define OUT_STRIDE (TGT_STEPS * INSZ)   // 1375
#define NCTA 128
#define NTHR 512

// ---------------- device scratch (no allocs allowed) ----------------
__device__ __align__(16) float g_h0[BATCH * HID];
__device__ __align__(16) float g_h1[BATCH * HID];
__device__ __align__(16) __half g_h0h[BATCH * HID];
__device__ __align__(16) __half g_h1h[BATCH * HID];
__device__ __align__(16) __half g_whh_h[NGATE * HID];   // fp16 Whh
__device__ __align__(16) __half g_wih_h[NGATE * KPAD];  // fp16 Wih (padded K)
__device__ __align__(16) __half g_encx_h[SRC_STEPS * BATCH * KPAD];
__device__ __align__(16) __half g_decx_h[TGT_STEPS * BATCH * KPAD];
__device__ int g_bar_ctr;               // FULL-GRID barrier (lockstep = L2 reuse)
__device__ int g_fc_ctr[16 * 32];       // group-local FC completion counters

// ---------------- PTX helpers (sm_80-class; valid on base sm_103) ----------
__device__ __forceinline__ uint32_t smem_u32(const void* p) {
    uint32_t a;
    asm("{ .reg .u64 t; cvta.to.shared.u64 t, %1; cvt.u32.u64 %0, t; }" : "=r"(a) : "l"(p));
    return a;
}
__device__ __forceinline__ void cp16(uint32_t dst, const void* src) {
    asm volatile("cp.async.cg.shared.global [%0], [%1], 16;"
                 :: "r"(dst), "l"(__cvta_generic_to_global(src)) : "memory");
}
#define CP_COMMIT() asm volatile("cp.async.commit_group;" ::: "memory")
#define CP_WAIT(n)  asm volatile("cp.async.wait_group %0;" :: "n"(n) : "memory")

__device__ __forceinline__ void ldsm4(uint32_t* r, uint32_t addr) {
    asm volatile("ldmatrix.sync.aligned.m8n8.x4.shared.b16 {%0,%1,%2,%3}, [%4];"
        : "=r"(r[0]), "=r"(r[1]), "=r"(r[2]), "=r"(r[3]) : "r"(addr));
}
__device__ __forceinline__ void mma16816(float* c, const uint32_t* a, uint32_t b0, uint32_t b1) {
    asm volatile("mma.sync.aligned.m16n8k16.row.col.f32.f16.f16.f32 "
        "{%0,%1,%2,%3}, {%4,%5,%6,%7}, {%8,%9}, {%0,%1,%2,%3};"
        : "+f"(c[0]), "+f"(c[1]), "+f"(c[2]), "+f"(c[3])
        : "r"(a[0]), "r"(a[1]), "r"(a[2]), "r"(a[3]), "r"(b0), "r"(b1));
}

__device__ __forceinline__ float fsig(float x) {
    return __fdividef(1.f, 1.f + __expf(-x));
}
__device__ __forceinline__ float ftanh(float x) {
    return 1.f - __fdividef(2.f, __expf(2.f * x) + 1.f);
}

// ---------------- geometry ----------------
// CTA: 128 batch rows x 64 hidden cols (= 192 gate-cols). 512 thr, 16 warps.
// warpM = wid&3 (32 rows), warpN = wid>>2 (48 gate-cols).
// Stages 0..7: Whh K=128 each; stage 8: Wih K=64 (x). Buffer = it&1.
#define ROWB 272
#define OFF_B 34816
#define STAGE 87040
#define EPW 200                 // epilogue fp32 tile, ALIASED onto stage bufs
#define GIN_OFF (2 * STAGE)     // 174080: smem h_n stash 128 x GINW fp32
#define GINW 66
#define BIAS_OFF (GIN_OFF + 128 * GINW * 4)     // 207872
#define SMEM_BYTES (BIAS_OFF + 4 * 64 * 4)      // 208896

// ---------------------------------------------------------------------------
// Persistent kernel: all 74 GRU steps + 25 decoder FC steps, one launch.
// ---------------------------------------------------------------------------
__global__ __launch_bounds__(NTHR, 1)
void seq2seq_persistent(const float* __restrict__ dec,
                        const float* __restrict__ bih, const float* __restrict__ bhh,
                        const float* __restrict__ fcw, const float* __restrict__ fcb,
                        float* __restrict__ out)
{
    extern __shared__ char smem[];
    const uint32_t sb = smem_u32(smem);
    const int tid = threadIdx.x;
    const int lane = tid & 31, wid = tid >> 5;
    const int warpM = wid & 3, warpN = wid >> 2;
    const int nT = blockIdx.x & 15, mT = blockIdx.x >> 4;
    const int mBase = mT * 128, nBase = nT * 64;
    volatile int* fcp = &g_fc_ctr[mT * 32];

    float* hf[2] = {g_h0, g_h1};
    __half* hsh[2] = {g_h0h, g_h1h};
    float* sgin = (float*)(smem + GIN_OFF);
    float* sbias = (float*)(smem + BIAS_OFF);   // [4][64]: r, z, n_hh, n_ih

    if (tid < 64) {
        int n = nBase + tid;
        sbias[tid]       = bih[n] + bhh[n];
        sbias[64 + tid]  = bih[HID + n] + bhh[HID + n];
        sbias[128 + tid] = bhh[2 * HID + n];
        sbias[192 + tid] = bih[2 * HID + n];
    }
    __syncthreads();

    // ldsm lane addressing (within stage buffer)
    const int arow = warpM * 32 + (lane & 15);
    const int acolh = (lane >> 4) << 3;
    const int bn = (lane & 7) + ((lane >> 4) << 3);
    const int bkh = ((lane >> 3) & 1) << 3;
    const uint32_t a_lofs = arow * ROWB + acolh * 2;
    const uint32_t b_lofs = (warpN * 48 + bn) * ROWB + bkh * 2;

    // ---- stage loaders ----
    auto load_whh = [&](const __half* hp, int it) {
        const uint32_t st = sb + (uint32_t)(it & 1) * STAGE;
        const int k0 = it * 128;
#pragma unroll
        for (int i = tid; i < 2048; i += NTHR) {         // A: 128r x 16c
            int row = i >> 4, c = i & 15;
            cp16(st + row * ROWB + c * 16,
                 hp + (long)(mBase + row) * HID + k0 + c * 8);
        }
#pragma unroll
        for (int i = tid; i < 3072; i += NTHR) {         // B: 192r x 16c
            int grow = i >> 4, c = i & 15;
            long wrow = (long)((grow >> 6) * HID + nBase + (grow & 63));
            cp16(st + OFF_B + grow * ROWB + c * 16,
                 g_whh_h + wrow * HID + k0 + c * 8);
        }
        CP_COMMIT();
    };
    auto load_wih = [&](const __half* xp) {
        const uint32_t st = sb;     // stage 8 -> buf 0
#pragma unroll
        for (int i = tid; i < 1024; i += NTHR) {         // A: 128r x 8c
            int row = i >> 3, c = i & 7;
            cp16(st + row * ROWB + c * 16,
                 xp + (long)(mBase + row) * KPAD + c * 8);
        }
#pragma unroll
        for (int i = tid; i < 1536; i += NTHR) {         // B: 192r x 8c
            int grow = i >> 3, c = i & 7;
            long wrow = (long)((grow >> 6) * HID + nBase + (grow & 63));
            cp16(st + OFF_B + grow * ROWB + c * 16,
                 g_wih_h + wrow * KPAD + c * 8);
        }
        CP_COMMIT();
    };

    int cur = 0, nbar = 0;
    bool pre0 = false;

    for (int t = 0; t < TOT_STEPS; t++) {
        const __half* ah = hsh[cur];
        const __half* xh = (t < SRC_STEPS)
            ? g_encx_h + (long)t * BATCH * KPAD
            : g_decx_h + (long)(t - SRC_STEPS) * BATCH * KPAD;

        float acc[2][6][4];
#pragma unroll
        for (int a0 = 0; a0 < 2; a0++)
#pragma unroll
            for (int i = 0; i < 6; i++)
#pragma unroll
                for (int j = 0; j < 4; j++) acc[a0][i][j] = 0.f;

        if (!pre0) load_whh(ah, 0);
        pre0 = false;

        // one k-block of compute (compile-time kb for unrolled scheduling)
        auto compute = [&](uint32_t st, int kb) {
            uint32_t Af[2][4], Bf[3][4];
            ldsm4(Af[0], st + a_lofs + kb * 32);
            ldsm4(Af[1], st + a_lofs + 16 * ROWB + kb * 32);
            const uint32_t bo = st + OFF_B + b_lofs + kb * 32;
#pragma unroll
            for (int g = 0; g < 3; g++) ldsm4(Bf[g], bo + g * (16 * ROWB));
#pragma unroll
            for (int mf = 0; mf < 2; mf++)
#pragma unroll
                for (int g = 0; g < 3; g++) {
                    mma16816(acc[mf][g * 2],     Af[mf], Bf[g][0], Bf[g][1]);
                    mma16816(acc[mf][g * 2 + 1], Af[mf], Bf[g][2], Bf[g][3]);
                }
        };

        for (int it = 0; it <= 8; it++) {
            if (it < 8) {
                if (it == 7) {
                    // Wih stage prefetch; decoder x needs prior step's FC (group)
                    if (t > SRC_STEPS) {
                        if (tid == 0) {
                            const int tgt = (t - SRC_STEPS) * 16;
                            while (*fcp < tgt) __nanosleep(32);
                            __threadfence();
                        }
                        __syncthreads();
                    }
                    load_wih(xh);
                } else {
                    load_whh(ah, it + 1);
                }
                CP_WAIT(1);
            } else {
                CP_WAIT(0);
            }
            __syncthreads();

            // ---- compute stage: compile-time-unrolled k loops ----
            {
                const uint32_t st = sb + (uint32_t)(it & 1) * STAGE;
                if (it < 8) {
#pragma unroll
                    for (int kb = 0; kb < 8; kb++) compute(st, kb);
                } else {
#pragma unroll
                    for (int kb = 0; kb < 4; kb++) compute(st, kb);
                }
            }

            // after last Whh stage: stash h_n (gate-cols 128..191), zero accs;
            // stage 8 (Wih) then deposits i_n into the zeroed slots.
            if (it == 7) {
                const int r0 = warpM * 32 + (lane >> 2);
#pragma unroll
                for (int mf = 0; mf < 2; mf++)
#pragma unroll
                    for (int j = 0; j < 6; j++) {
                        const int gc = warpN * 48 + j * 8;
                        if (gc >= 128) {
                            int jl = gc - 128 + (lane & 3) * 2;
                            int rr = r0 + mf * 16;
                            *(float2*)&sgin[rr * GINW + jl] =
                                make_float2(acc[mf][j][0], acc[mf][j][1]);
                            *(float2*)&sgin[(rr + 8) * GINW + jl] =
                                make_float2(acc[mf][j][2], acc[mf][j][3]);
                            acc[mf][j][0] = acc[mf][j][1] = 0.f;
                            acc[mf][j][2] = acc[mf][j][3] = 0.f;
                        }
                    }
            }
            __syncthreads();
        }

        // ---- epilogue: frags -> ep smem (aliases stage bufs), gates, h ----
        float* ep = (float*)smem;
        {
            const int r0 = warpM * 32 + (lane >> 2);
#pragma unroll
            for (int mf = 0; mf < 2; mf++)
#pragma unroll
                for (int j = 0; j < 6; j++) {
                    int c = warpN * 48 + j * 8 + (lane & 3) * 2;
                    int rr = r0 + mf * 16;
                    *(float2*)&ep[rr * EPW + c] =
                        make_float2(acc[mf][j][0], acc[mf][j][1]);
                    *(float2*)&ep[(rr + 8) * EPW + c] =
                        make_float2(acc[mf][j][2], acc[mf][j][3]);
                }
        }
        __syncthreads();

        {
            const float* h_in = hf[cur];
            float* h_out = hf[cur ^ 1];
            __half* hoh = hsh[cur ^ 1];
            for (int i = tid; i < 4096; i += NTHR) {    // pairs
                int m = i >> 5, jp = (i & 31) * 2;
                long gi = (long)(mBase + m) * HID + nBase + jp;
                float2 rr = *(float2*)&ep[m * EPW + jp];
                float2 zz = *(float2*)&ep[m * EPW + 64 + jp];
                float2 ii = *(float2*)&ep[m * EPW + 128 + jp];
                float2 hh = *(float2*)&sgin[m * GINW + jp];
                float2 br = *(float2*)&sbias[jp];
                float2 bz = *(float2*)&sbias[64 + jp];
                float2 bh = *(float2*)&sbias[128 + jp];
                float2 bi = *(float2*)&sbias[192 + jp];
                float2 hp = *(float2*)&h_in[gi];
                float r0 = fsig(rr.x + br.x), r1 = fsig(rr.y + br.y);
                float z0 = fsig(zz.x + bz.x), z1 = fsig(zz.y + bz.y);
                float n0 = ftanh(ii.x + bi.x + r0 * (hh.x + bh.x));
                float n1 = ftanh(ii.y + bi.y + r1 * (hh.y + bh.y));
                float o0 = (1.f - z0) * n0 + z0 * hp.x;
                float o1 = (1.f - z1) * n1 + z1 * hp.y;
                *(float2*)&h_out[gi] = make_float2(o0, o1);
                *(__half2*)&hoh[gi] = __floats2half2_rn(o0, o1);
            }
        }
        cur ^= 1;

        // ---- FULL-GRID barrier (lockstep -> Whh L2 reuse across groups) ----
        nbar++;
        __syncthreads();
        if (tid == 0) {
            __threadfence();
            atomicAdd(&g_bar_ctr, 1);
            while (*(volatile int*)&g_bar_ctr < nbar * NCTA) __nanosleep(32);
            __threadfence();
        }
        __syncthreads();

        // ---- pre-issue next step's stage-0 load (hides fill under FC) ----
        if (t + 1 < TOT_STEPS) {
            load_whh(hsh[cur], 0);
            pre0 = true;
        }

        // ---- decoder FC (overlapped: consumers wait via fc_ctr at stage 7) --
        if (t >= SRC_STEPS) {
            const int td = t - SRC_STEPS;
            const float* hcur = hf[cur];
            const int b = blockIdx.x * 8 + (wid >> 1);
            const int half = wid & 1;
            float hreg[32];
#pragma unroll
            for (int i = 0; i < 32; i++)
                hreg[i] = __ldcg(&hcur[(long)b * HID + lane + 32 * i]);
            const int o0 = half * 28, o1 = half ? INSZ : 28;
            for (int o = o0; o < o1; o++) {
                float s = 0.f;
#pragma unroll
                for (int i = 0; i < 32; i++)
                    s += hreg[i] * fcw[(long)o * HID + lane + 32 * i];
#pragma unroll
                for (int off = 16; off; off >>= 1) s += __shfl_xor_sync(0xffffffffu, s, off);
                if (lane == 0) {
                    float inp = (td == 0) ? dec[(long)b * OUT_STRIDE + o]
                                          : out[(long)b * OUT_STRIDE + (td - 1) * INSZ + o];
                    float v = inp + s + fcb[o];
                    out[(long)b * OUT_STRIDE + td * INSZ + o] = v;
                    if (td < TGT_STEPS - 1) {
                        long x = (long)(td + 1) * BATCH * KPAD + (long)b * KPAD + o;
                        g_decx_h[x] = __float2half_rn(v);
                    }
                }
            }
            if (td < TGT_STEPS - 1 && half == 1 && lane < KPAD - INSZ) {
                long x = (long)(td + 1) * BATCH * KPAD + (long)b * KPAD + INSZ + lane;
                g_decx_h[x] = __float2half_rn(0.f);
            }
            __syncthreads();
            if (tid == 0) {
                __threadfence();
                atomicAdd(&g_fc_ctr[mT * 32], 1);
            }
        }
    }
}

// ---------------- merged prep kernel ----------------
#define P_WHH  ((long)NGATE * HID)
#define P_WIH  ((long)NGATE * KPAD)
#define P_ENC  ((long)SRC_STEPS * BATCH * KPAD)
#define P_DEC  ((long)BATCH * KPAD)
#define P_ST   ((long)BATCH * HID)
#define P_TOT  (P_WHH + P_WIH + P_ENC + P_DEC + P_ST)

__global__ void prep_kernel(const float* __restrict__ Whh, const float* __restrict__ Wih,
                            const float* __restrict__ enc, const float* __restrict__ dec)
{
    long i = (long)blockIdx.x * 256 + threadIdx.x;
    if (blockIdx.x == 0) {
        if (threadIdx.x == 0) g_bar_ctr = 0;
        if (threadIdx.x < 16 * 32) g_fc_ctr[threadIdx.x] = 0;
    }
    if (i < P_WHH) { g_whh_h[i] = __float2half_rn(Whh[i]); return; }
    i -= P_WHH;
    if (i < P_WIH) {
        int row = (int)(i >> 6), k = (int)(i & 63);
        float v = (k < INSZ) ? Wih[(long)row * INSZ + k] : 0.f;
        g_wih_h[i] = __float2half_rn(v);
        return;
    }
    i -= P_WIH;
    if (i < P_ENC) {
        int t = (int)(i / (BATCH * KPAD));
        int r = (int)(i % (BATCH * KPAD));
        int b = r >> 6, k = r & 63;
        float v = (k < INSZ) ? enc[((long)b * 50 + t) * INSZ + k] : 0.f;
        g_encx_h[i] = __float2half_rn(v);
        return;
    }
    i -= P_ENC;
    if (i < P_DEC) {
        int b = (int)(i >> 6), k = (int)(i & 63);
        float v = (k < INSZ) ? dec[(long)b * OUT_STRIDE + k] : 0.f;
        g_decx_h[i] = __float2half_rn(v);
        return;
    }
    i -= P_DEC;
    if (i < P_ST) {
        g_h0[i] = 0.f;
        g_h0h[i] = __float2half_rn(0.f);
    }
}

extern "C" void kernel_launch(void* const* d_in, const int* in_sizes, int n_in,
                              void* d_out, int out_size)
{
    const float* enc = (const float*)d_in[0];
    const float* dec = (const float*)d_in[1];
    const float* Wih = (const float*)d_in[2];
    const float* Whh = (const float*)d_in[3];
    const float* bih = (const float*)d_in[4];
    const float* bhh = (const float*)d_in[5];
    const float* fcw = (const float*)d_in[6];
    const float* fcb = (const float*)d_in[7];
    float* out = (float*)d_out;

    cudaFuncSetAttribute(seq2seq_persistent,
                         cudaFuncAttributeMaxDynamicSharedMemorySize, SMEM_BYTES);

    prep_kernel<<<(int)((P_TOT + 255) / 256), 256>>>(Whh, Wih, enc, dec);
    seq2seq_persistent<<<NCTA, NTHR, SMEM_BYTES>>>(dec, bih, bhh, fcw, fcb, out);
}